// round 16
// baseline (speedup 1.0000x reference)
#include <cuda_runtime.h>
#include <cuda_bf16.h>
#include <cuda_fp16.h>
#include <cstdint>

#define SEQ 2048
#define NB  8

typedef unsigned long long ull;
typedef unsigned int u32;

// ---------------- device scratch (allocation-free per harness rules) ----------------
__device__ float g_S[(size_t)NB * SEQ * SEQ];                    // 134 MB logits / P
#define N4 ((size_t)NB * SEQ * SEQ / 4)
__device__ ull g_Qh[N4]; __device__ ull g_Ql[N4];                // bf16 splits of Q, K
__device__ ull g_Kh[N4]; __device__ ull g_Kl[N4];
__device__ ull g_Vh[N4]; __device__ ull g_Vl[N4];                // fp16 splits of V
__device__ ull g_Ph[N4];                                         // fp16 of P^T

// ---------------- helpers ----------------
__device__ __forceinline__ u32 smem_u32(const void* p) {
    u32 a;
    asm("{ .reg .u64 t; cvta.to.shared.u64 t, %1; cvt.u32.u64 %0, t; }" : "=r"(a) : "l"(p));
    return a;
}
__device__ __forceinline__ void cpa16(u32 dst, const void* src) {
    asm volatile("cp.async.cg.shared.global [%0], [%1], 16;" :: "r"(dst), "l"(src));
}
#define CP_COMMIT()  asm volatile("cp.async.commit_group;")
#define CP_WAIT0()   asm volatile("cp.async.wait_group 0;" ::: "memory")

#define LDM4(R, addr)                                                         \
    asm volatile("ldmatrix.sync.aligned.m8n8.x4.shared.b16 {%0,%1,%2,%3}, [%4];" \
                 : "=r"((R)[0]), "=r"((R)[1]), "=r"((R)[2]), "=r"((R)[3])     \
                 : "r"(addr))
#define MMA_BF16(d, a, b)                                                     \
    asm volatile("mma.sync.aligned.m16n8k16.row.col.f32.bf16.bf16.f32 "       \
                 "{%0,%1,%2,%3}, {%4,%5,%6,%7}, {%8,%9}, {%0,%1,%2,%3};"      \
                 : "+f"((d)[0]), "+f"((d)[1]), "+f"((d)[2]), "+f"((d)[3])     \
                 : "r"((a)[0]), "r"((a)[1]), "r"((a)[2]), "r"((a)[3]),        \
                   "r"((b)[0]), "r"((b)[1]))
#define MMA_F16(d, a, b)                                                      \
    asm volatile("mma.sync.aligned.m16n8k16.row.col.f32.f16.f16.f32 "         \
                 "{%0,%1,%2,%3}, {%4,%5,%6,%7}, {%8,%9}, {%0,%1,%2,%3};"      \
                 : "+f"((d)[0]), "+f"((d)[1]), "+f"((d)[2]), "+f"((d)[3])     \
                 : "r"((a)[0]), "r"((a)[1]), "r"((a)[2]), "r"((a)[3]),        \
                   "r"((b)[0]), "r"((b)[1]))

// SW128 swizzle (Swizzle<3,4,3>), tile base must be 1024B aligned
#define SWZ(x) ((x) ^ (((x) >> 3) & 0x70))

__device__ __forceinline__ ull pack4(__nv_bfloat16 a, __nv_bfloat16 b,
                                     __nv_bfloat16 c, __nv_bfloat16 d) {
    return (ull)__bfloat16_as_ushort(a)
         | ((ull)__bfloat16_as_ushort(b) << 16)
         | ((ull)__bfloat16_as_ushort(c) << 32)
         | ((ull)__bfloat16_as_ushort(d) << 48);
}
__device__ __forceinline__ ull pack4h(__half a, __half b, __half c, __half d) {
    return (ull)__half_as_ushort(a)
         | ((ull)__half_as_ushort(b) << 16)
         | ((ull)__half_as_ushort(c) << 32)
         | ((ull)__half_as_ushort(d) << 48);
}

// ---------------- split kernels ----------------
__global__ __launch_bounds__(256)
void split_bf16(const float4* __restrict__ in, ull* __restrict__ hi, ull* __restrict__ lo) {
    size_t i = (size_t)blockIdx.x * 256 + threadIdx.x;
    float4 v = in[i];
    __nv_bfloat16 h0 = __float2bfloat16(v.x), h1 = __float2bfloat16(v.y);
    __nv_bfloat16 h2 = __float2bfloat16(v.z), h3 = __float2bfloat16(v.w);
    __nv_bfloat16 l0 = __float2bfloat16(v.x - __bfloat162float(h0));
    __nv_bfloat16 l1 = __float2bfloat16(v.y - __bfloat162float(h1));
    __nv_bfloat16 l2 = __float2bfloat16(v.z - __bfloat162float(h2));
    __nv_bfloat16 l3 = __float2bfloat16(v.w - __bfloat162float(h3));
    hi[i] = pack4(h0, h1, h2, h3);
    lo[i] = pack4(l0, l1, l2, l3);
}
__global__ __launch_bounds__(256)
void split_f16(const float4* __restrict__ in, ull* __restrict__ hi, ull* __restrict__ lo) {
    size_t i = (size_t)blockIdx.x * 256 + threadIdx.x;
    float4 v = in[i];
    __half h0 = __float2half(v.x), h1 = __float2half(v.y);
    __half h2 = __float2half(v.z), h3 = __float2half(v.w);
    __half l0 = __float2half(v.x - __half2float(h0));
    __half l1 = __float2half(v.y - __half2float(h1));
    __half l2 = __float2half(v.z - __half2float(h2));
    __half l3 = __float2half(v.w - __half2float(h3));
    hi[i] = pack4h(h0, h1, h2, h3);
    lo[i] = pack4h(l0, l1, l2, l3);
}

// ================= GEMM1: bf16x3, D[m,n] = sum_k A[m,k]*B[n,k] =================
// 128x128 CTA tile, K-chunk 64, 2-stage cp.async, 16 warps (32x32 warp tile,
// 4Mx4N layout -> 4 warps per SMSP), 1 CTA/SM.
#define TILE_B    16384             // 128 rows * 128B (64 bf16)
#define CHUNK1_B  (4 * TILE_B)      // Ah, Al, Bh, Bl
#define SMEM1_DYN (1024 + 2 * CHUNK1_B)

__global__ __launch_bounds__(512, 1)
void gemm_bf16x3(const __nv_bfloat16* __restrict__ Ah, const __nv_bfloat16* __restrict__ Al,
                 const __nv_bfloat16* __restrict__ Bh, const __nv_bfloat16* __restrict__ Bl,
                 float* __restrict__ C)
{
    extern __shared__ char dsm[];
    const int tid  = threadIdx.x;
    const int warp = tid >> 5;
    const int lane = tid & 31;
    const int b  = blockIdx.z;
    const int m0 = blockIdx.y * 128;
    const int n0 = blockIdx.x * 128;

    const u32 base = (smem_u32(dsm) + 1023u) & ~1023u;
    const int wm = (warp >> 2) * 32;     // 0,32,64,96
    const int wn = (warp & 3) * 32;      // 0,32,64,96

    // loader: 128 threads per tile (Ah/Al/Bh/Bl); 8 segs x 16 row-bases; 8 rows each
    const size_t bs = (size_t)SEQ * SEQ;
    const int tsel = tid >> 7;        // 0:Ah 1:Al 2:Bh 3:Bl
    const int tt   = tid & 127;
    const int seg  = tt & 7;          // 16B segment within 128B row
    const int rb   = tt >> 3;         // row base 0..15
    const __nv_bfloat16* gbase;
    {
        size_t aoff = (size_t)b * bs + (size_t)m0 * SEQ;
        size_t boff = (size_t)b * bs + (size_t)n0 * SEQ;
        gbase = (tsel == 0) ? Ah + aoff : (tsel == 1) ? Al + aoff
              : (tsel == 2) ? Bh + boff : Bl + boff;
        gbase += (size_t)rb * SEQ + seg * 8;
    }
    u32 soff[8];
#pragma unroll
    for (int j = 0; j < 8; j++)
        soff[j] = SWZ((u32)((rb + 16 * j) * 128 + seg * 16));
    const u32 myTile = base + (u32)tsel * TILE_B;

    const int aRow = ((lane >> 3) & 1) * 8 + (lane & 7);
    const int aCol = (lane >> 4) << 4;
    const int bRow = ((lane >> 4) << 3) + (lane & 7);
    const int bCol = ((lane >> 3) & 1) << 4;

    float acc[2][4][4];
#pragma unroll
    for (int mt = 0; mt < 2; mt++)
#pragma unroll
        for (int nt = 0; nt < 4; nt++)
#pragma unroll
            for (int r = 0; r < 4; r++) acc[mt][nt][r] = 0.0f;

    const int NCHUNK = SEQ / 64;   // 32

    // prologue: chunk 0 -> buffer 0
#pragma unroll
    for (int j = 0; j < 8; j++)
        cpa16(myTile + soff[j], gbase + (size_t)(16 * j) * SEQ);
    CP_COMMIT();
    CP_WAIT0();
    __syncthreads();

    for (int i = 0; i < NCHUNK; i++) {
        const int buf = i & 1;

        if (i + 1 < NCHUNK) {
            const __nv_bfloat16* g = gbase + (i + 1) * 64;
            const u32 st = myTile + (buf ^ 1) * CHUNK1_B;
#pragma unroll
            for (int j = 0; j < 8; j++)
                cpa16(st + soff[j], g + (size_t)(16 * j) * SEQ);
            CP_COMMIT();
        }

        const u32 sb  = base + buf * CHUNK1_B;
        const u32 tAh = sb;
        const u32 tAl = sb + TILE_B;
        const u32 tBh = sb + 2 * TILE_B;
        const u32 tBl = sb + 3 * TILE_B;

#pragma unroll
        for (int ks = 0; ks < 4; ks++) {
            const int kb = ks * 32;
            u32 ah[2][4], al[2][4];
#pragma unroll
            for (int mt = 0; mt < 2; mt++) {
                u32 ro = SWZ((u32)((wm + mt * 16 + aRow) * 128 + kb + aCol));
                LDM4(ah[mt], tAh + ro);
                LDM4(al[mt], tAl + ro);
            }
            u32 bh[2][4], bl[2][4];
#pragma unroll
            for (int ng = 0; ng < 2; ng++) {
                u32 ro = SWZ((u32)((wn + ng * 16 + bRow) * 128 + kb + bCol));
                LDM4(bh[ng], tBh + ro);
                LDM4(bl[ng], tBl + ro);
            }
#pragma unroll
            for (int mt = 0; mt < 2; mt++) {
#pragma unroll
                for (int nt = 0; nt < 4; nt++) {
                    const u32* ph = &bh[nt >> 1][(nt & 1) * 2];
                    const u32* pl = &bl[nt >> 1][(nt & 1) * 2];
                    MMA_BF16(acc[mt][nt], ah[mt], ph);
                    MMA_BF16(acc[mt][nt], ah[mt], pl);
                    MMA_BF16(acc[mt][nt], al[mt], ph);
                }
            }
        }

        CP_WAIT0();
        __syncthreads();
    }

    float* Cb = C + (size_t)b * bs;
    const int rrow = lane >> 2;
    const int rcol = (lane & 3) * 2;
#pragma unroll
    for (int mt = 0; mt < 2; mt++) {
#pragma unroll
        for (int nt = 0; nt < 4; nt++) {
            const int row = m0 + wm + mt * 16 + rrow;
            const int col = n0 + wn + nt * 8 + rcol;
            float2 v0; v0.x = acc[mt][nt][0]; v0.y = acc[mt][nt][1];
            float2 v1; v1.x = acc[mt][nt][2]; v1.y = acc[mt][nt][3];
            *(float2*)&Cb[(size_t)row * SEQ + col]       = v0;
            *(float2*)&Cb[(size_t)(row + 8) * SEQ + col] = v1;
        }
    }
}

// ================= GEMM2: fp16 2-product, D[m,n] = sum_k A[m,k]*B[n,k] =================
// A = Ah+Al (fp16 split of V), B = Bh (single fp16 P^T). Computes Ah*Bh + Al*Bh.
#define CHUNK2_B  (3 * TILE_B)      // Vh, Vl, Ph
#define SMEM2_DYN (1024 + 2 * CHUNK2_B)

__global__ __launch_bounds__(512, 1)
void gemm_f16x2(const __half* __restrict__ Ah, const __half* __restrict__ Al,
                const __half* __restrict__ Bh, float* __restrict__ C)
{
    extern __shared__ char dsm[];
    const int tid  = threadIdx.x;
    const int warp = tid >> 5;
    const int lane = tid & 31;
    const int b  = blockIdx.z;
    const int m0 = blockIdx.y * 128;
    const int n0 = blockIdx.x * 128;

    const u32 base = (smem_u32(dsm) + 1023u) & ~1023u;
    const int wm = (warp >> 2) * 32;
    const int wn = (warp & 3) * 32;

    const size_t bs = (size_t)SEQ * SEQ;
    const int tsel = tid >> 7;        // 0:Vh 1:Vl 2:Ph 3:idle
    const int tt   = tid & 127;
    const int seg  = tt & 7;
    const int rb   = tt >> 3;
    const __half* gbase = nullptr;
    if (tsel < 3) {
        size_t aoff = (size_t)b * bs + (size_t)m0 * SEQ;
        size_t boff = (size_t)b * bs + (size_t)n0 * SEQ;
        gbase = (tsel == 0) ? Ah + aoff : (tsel == 1) ? Al + aoff : Bh + boff;
        gbase += (size_t)rb * SEQ + seg * 8;
    }
    u32 soff[8];
#pragma unroll
    for (int j = 0; j < 8; j++)
        soff[j] = SWZ((u32)((rb + 16 * j) * 128 + seg * 16));
    const u32 myOff = (u32)tsel * TILE_B;

    const int aRow = ((lane >> 3) & 1) * 8 + (lane & 7);
    const int aCol = (lane >> 4) << 4;
    const int bRow = ((lane >> 4) << 3) + (lane & 7);
    const int bCol = ((lane >> 3) & 1) << 4;

    float acc[2][4][4];
#pragma unroll
    for (int mt = 0; mt < 2; mt++)
#pragma unroll
        for (int nt = 0; nt < 4; nt++)
#pragma unroll
            for (int r = 0; r < 4; r++) acc[mt][nt][r] = 0.0f;

    const int NCHUNK = SEQ / 64;

    if (tsel < 3) {
#pragma unroll
        for (int j = 0; j < 8; j++)
            cpa16(base + myOff + soff[j], gbase + (size_t)(16 * j) * SEQ);
    }
    CP_COMMIT();
    CP_WAIT0();
    __syncthreads();

    for (int i = 0; i < NCHUNK; i++) {
        const int buf = i & 1;

        if (i + 1 < NCHUNK && tsel < 3) {
            const __half* g = gbase + (i + 1) * 64;
            const u32 st = base + (buf ^ 1) * CHUNK2_B + myOff;
#pragma unroll
            for (int j = 0; j < 8; j++)
                cpa16(st + soff[j], g + (size_t)(16 * j) * SEQ);
        }
        CP_COMMIT();

        const u32 sb  = base + buf * CHUNK2_B;
        const u32 tVh = sb;
        const u32 tVl = sb + TILE_B;
        const u32 tPh = sb + 2 * TILE_B;

#pragma unroll
        for (int ks = 0; ks < 4; ks++) {
            const int kb = ks * 32;
            u32 ah[2][4], al[2][4];
#pragma unroll
            for (int mt = 0; mt < 2; mt++) {
                u32 ro = SWZ((u32)((wm + mt * 16 + aRow) * 128 + kb + aCol));
                LDM4(ah[mt], tVh + ro);
                LDM4(al[mt], tVl + ro);
            }
            u32 bh[2][4];
#pragma unroll
            for (int ng = 0; ng < 2; ng++) {
                u32 ro = SWZ((u32)((wn + ng * 16 + bRow) * 128 + kb + bCol));
                LDM4(bh[ng], tPh + ro);
            }
#pragma unroll
            for (int mt = 0; mt < 2; mt++) {
#pragma unroll
                for (int nt = 0; nt < 4; nt++) {
                    const u32* ph = &bh[nt >> 1][(nt & 1) * 2];
                    MMA_F16(acc[mt][nt], ah[mt], ph);
                    MMA_F16(acc[mt][nt], al[mt], ph);
                }
            }
        }

        CP_WAIT0();
        __syncthreads();
    }

    float* Cb = C + (size_t)b * bs;
    const int rrow = lane >> 2;
    const int rcol = (lane & 3) * 2;
#pragma unroll
    for (int mt = 0; mt < 2; mt++) {
#pragma unroll
        for (int nt = 0; nt < 4; nt++) {
            const int row = m0 + wm + mt * 16 + rrow;
            const int col = n0 + wn + nt * 8 + rcol;
            float2 v0; v0.x = acc[mt][nt][0]; v0.y = acc[mt][nt][1];
            float2 v1; v1.x = acc[mt][nt][2]; v1.y = acc[mt][nt][3];
            *(float2*)&Cb[(size_t)row * SEQ + col]       = v0;
            *(float2*)&Cb[(size_t)(row + 8) * SEQ + col] = v1;
        }
    }
}

// ---------------- row softmax (validated) ----------------
__global__ __launch_bounds__(256)
void softmax_rows(float* __restrict__ P)
{
    __shared__ float redm[8];
    __shared__ float reds[8];

    float* p = P + (size_t)blockIdx.x * SEQ;
    const int tid = threadIdx.x;

    float4 v0 = *(const float4*)&p[tid * 8];
    float4 v1 = *(const float4*)&p[tid * 8 + 4];

    float m = fmaxf(fmaxf(fmaxf(v0.x, v0.y), fmaxf(v0.z, v0.w)),
                    fmaxf(fmaxf(v1.x, v1.y), fmaxf(v1.z, v1.w)));
#pragma unroll
    for (int o = 16; o > 0; o >>= 1)
        m = fmaxf(m, __shfl_xor_sync(0xffffffffu, m, o));
    if ((tid & 31) == 0) redm[tid >> 5] = m;
    __syncthreads();
    float bm = redm[0];
#pragma unroll
    for (int i = 1; i < 8; i++) bm = fmaxf(bm, redm[i]);

    float e[8];
    e[0] = __expf(v0.x - bm); e[1] = __expf(v0.y - bm);
    e[2] = __expf(v0.z - bm); e[3] = __expf(v0.w - bm);
    e[4] = __expf(v1.x - bm); e[5] = __expf(v1.y - bm);
    e[6] = __expf(v1.z - bm); e[7] = __expf(v1.w - bm);
    float s = ((e[0] + e[1]) + (e[2] + e[3])) + ((e[4] + e[5]) + (e[6] + e[7]));
#pragma unroll
    for (int o = 16; o > 0; o >>= 1)
        s += __shfl_xor_sync(0xffffffffu, s, o);
    if ((tid & 31) == 0) reds[tid >> 5] = s;
    __syncthreads();
    float total = reds[0];
#pragma unroll
    for (int i = 1; i < 8; i++) total += reds[i];

    const float r = 1.0f / total;
    v0.x = e[0] * r; v0.y = e[1] * r; v0.z = e[2] * r; v0.w = e[3] * r;
    v1.x = e[4] * r; v1.y = e[5] * r; v1.z = e[6] * r; v1.w = e[7] * r;
    *(float4*)&p[tid * 8]     = v0;
    *(float4*)&p[tid * 8 + 4] = v1;
}

// ---------------- transpose + fp16 convert: P[d,k] -> Pt[k,d] ----------------
__global__ __launch_bounds__(256)
void transpose_f16(const float* __restrict__ P, ull* __restrict__ hiT)
{
    __shared__ float s[64][65];
    const int b  = blockIdx.z;
    const int d0 = blockIdx.y * 64;
    const int k0 = blockIdx.x * 64;
    const float* Pb = P + (size_t)b * SEQ * SEQ;
    const int t  = threadIdx.x;
    const int c4 = (t & 15) * 4;
    const int r  = t >> 4;

#pragma unroll
    for (int j = 0; j < 4; j++) {
        int row = r + 16 * j;
        float4 v = *(const float4*)&Pb[(size_t)(d0 + row) * SEQ + k0 + c4];
        s[row][c4 + 0] = v.x; s[row][c4 + 1] = v.y;
        s[row][c4 + 2] = v.z; s[row][c4 + 3] = v.w;
    }
    __syncthreads();
#pragma unroll
    for (int j = 0; j < 4; j++) {
        int trow = r + 16 * j;
        __half h0 = __float2half(s[c4 + 0][trow]);
        __half h1 = __float2half(s[c4 + 1][trow]);
        __half h2 = __float2half(s[c4 + 2][trow]);
        __half h3 = __float2half(s[c4 + 3][trow]);
        size_t oi = ((size_t)b * SEQ * SEQ + (size_t)(k0 + trow) * SEQ + d0 + c4) >> 2;
        hiT[oi] = pack4h(h0, h1, h2, h3);
    }
}

// ---------------- launcher ----------------
extern "C" void kernel_launch(void* const* d_in, const int* in_sizes, int n_in,
                              void* d_out, int out_size)
{
    const float* q = (const float*)d_in[0];
    const float* k = (const float*)d_in[1];
    const float* v = (const float*)d_in[2];
    // d_in[3] = attn_mask: all zeros, unused by the reference math.
    float* out = (float*)d_out;

    float *S = nullptr;
    ull *Qh, *Ql, *Kh, *Kl, *Vh, *Vl, *Ph;
    cudaGetSymbolAddress((void**)&S,  g_S);
    cudaGetSymbolAddress((void**)&Qh, g_Qh); cudaGetSymbolAddress((void**)&Ql, g_Ql);
    cudaGetSymbolAddress((void**)&Kh, g_Kh); cudaGetSymbolAddress((void**)&Kl, g_Kl);
    cudaGetSymbolAddress((void**)&Vh, g_Vh); cudaGetSymbolAddress((void**)&Vl, g_Vl);
    cudaGetSymbolAddress((void**)&Ph, g_Ph);

    cudaFuncSetAttribute(gemm_bf16x3, cudaFuncAttributeMaxDynamicSharedMemorySize, SMEM1_DYN);
    cudaFuncSetAttribute(gemm_f16x2,  cudaFuncAttributeMaxDynamicSharedMemorySize, SMEM2_DYN);

    const int splitBlocks = (int)(N4 / 256);          // 32768
    split_bf16<<<splitBlocks, 256>>>((const float4*)q, Qh, Ql);
    split_bf16<<<splitBlocks, 256>>>((const float4*)k, Kh, Kl);
    split_f16 <<<splitBlocks, 256>>>((const float4*)v, Vh, Vl);

    const dim3 grid(SEQ / 128, SEQ / 128, NB);        // (16, 16, 8) = 2048 CTAs
    // 1) S[q,k] = sum_d Q[q,d] K[k,d]   (bf16x3)
    gemm_bf16x3<<<grid, 512, SMEM1_DYN>>>((const __nv_bfloat16*)Qh, (const __nv_bfloat16*)Ql,
                                          (const __nv_bfloat16*)Kh, (const __nv_bfloat16*)Kl, S);
    // 2) row softmax in place
    softmax_rows<<<NB * SEQ, 256>>>(S);
    // 3) Pt[k2,d] = fp16(P[d,k2])
    transpose_f16<<<dim3(SEQ / 64, SEQ / 64, NB), 256>>>(S, Ph);
    // 4) out[s,k2] = sum_d V[s,d] Pt[k2,d]   (fp16 2-product)
    gemm_f16x2<<<grid, 512, SMEM2_DYN>>>((const __half*)Vh, (const __half*)Vl,
                                         (const __half*)Ph, out);
}

// round 17
// speedup vs baseline: 1.1514x; 1.1514x over previous
#include <cuda_runtime.h>
#include <cuda_bf16.h>
#include <cuda_fp16.h>
#include <cstdint>

#define SEQ 2048
#define NB  8

typedef unsigned long long ull;
typedef unsigned int u32;

// ---------------- device scratch (allocation-free per harness rules) ----------------
__device__ float g_S[(size_t)NB * SEQ * SEQ];                    // 134 MB logits / P
#define N4 ((size_t)NB * SEQ * SEQ / 4)
__device__ ull g_Qh[N4]; __device__ ull g_Ql[N4];                // bf16 splits of Q, K
__device__ ull g_Kh[N4]; __device__ ull g_Kl[N4];
__device__ ull g_Vh[N4];                                         // fp16 of V
__device__ ull g_Ph[N4];                                         // fp16 of P^T

// ---------------- helpers ----------------
__device__ __forceinline__ u32 smem_u32(const void* p) {
    u32 a;
    asm("{ .reg .u64 t; cvta.to.shared.u64 t, %1; cvt.u32.u64 %0, t; }" : "=r"(a) : "l"(p));
    return a;
}
__device__ __forceinline__ void cpa16(u32 dst, const void* src) {
    asm volatile("cp.async.cg.shared.global [%0], [%1], 16;" :: "r"(dst), "l"(src));
}
#define CP_COMMIT()  asm volatile("cp.async.commit_group;")
#define CP_WAIT0()   asm volatile("cp.async.wait_group 0;" ::: "memory")

#define LDM4(R, addr)                                                         \
    asm volatile("ldmatrix.sync.aligned.m8n8.x4.shared.b16 {%0,%1,%2,%3}, [%4];" \
                 : "=r"((R)[0]), "=r"((R)[1]), "=r"((R)[2]), "=r"((R)[3])     \
                 : "r"(addr))
#define MMA_BF16(d, a, b)                                                     \
    asm volatile("mma.sync.aligned.m16n8k16.row.col.f32.bf16.bf16.f32 "       \
                 "{%0,%1,%2,%3}, {%4,%5,%6,%7}, {%8,%9}, {%0,%1,%2,%3};"      \
                 : "+f"((d)[0]), "+f"((d)[1]), "+f"((d)[2]), "+f"((d)[3])     \
                 : "r"((a)[0]), "r"((a)[1]), "r"((a)[2]), "r"((a)[3]),        \
                   "r"((b)[0]), "r"((b)[1]))
#define MMA_F16(d, a, b)                                                      \
    asm volatile("mma.sync.aligned.m16n8k16.row.col.f32.f16.f16.f32 "         \
                 "{%0,%1,%2,%3}, {%4,%5,%6,%7}, {%8,%9}, {%0,%1,%2,%3};"      \
                 : "+f"((d)[0]), "+f"((d)[1]), "+f"((d)[2]), "+f"((d)[3])     \
                 : "r"((a)[0]), "r"((a)[1]), "r"((a)[2]), "r"((a)[3]),        \
                   "r"((b)[0]), "r"((b)[1]))

// SW128 swizzle (Swizzle<3,4,3>), tile base must be 1024B aligned
#define SWZ(x) ((x) ^ (((x) >> 3) & 0x70))

__device__ __forceinline__ ull pack4(__nv_bfloat16 a, __nv_bfloat16 b,
                                     __nv_bfloat16 c, __nv_bfloat16 d) {
    return (ull)__bfloat16_as_ushort(a)
         | ((ull)__bfloat16_as_ushort(b) << 16)
         | ((ull)__bfloat16_as_ushort(c) << 32)
         | ((ull)__bfloat16_as_ushort(d) << 48);
}
__device__ __forceinline__ ull pack4h(__half a, __half b, __half c, __half d) {
    return (ull)__half_as_ushort(a)
         | ((ull)__half_as_ushort(b) << 16)
         | ((ull)__half_as_ushort(c) << 32)
         | ((ull)__half_as_ushort(d) << 48);
}

// ---------------- split / convert kernels ----------------
__global__ __launch_bounds__(256)
void split_bf16(const float4* __restrict__ in, ull* __restrict__ hi, ull* __restrict__ lo) {
    size_t i = (size_t)blockIdx.x * 256 + threadIdx.x;
    float4 v = in[i];
    __nv_bfloat16 h0 = __float2bfloat16(v.x), h1 = __float2bfloat16(v.y);
    __nv_bfloat16 h2 = __float2bfloat16(v.z), h3 = __float2bfloat16(v.w);
    __nv_bfloat16 l0 = __float2bfloat16(v.x - __bfloat162float(h0));
    __nv_bfloat16 l1 = __float2bfloat16(v.y - __bfloat162float(h1));
    __nv_bfloat16 l2 = __float2bfloat16(v.z - __bfloat162float(h2));
    __nv_bfloat16 l3 = __float2bfloat16(v.w - __bfloat162float(h3));
    hi[i] = pack4(h0, h1, h2, h3);
    lo[i] = pack4(l0, l1, l2, l3);
}
__global__ __launch_bounds__(256)
void convert_f16(const float4* __restrict__ in, ull* __restrict__ hi) {
    size_t i = (size_t)blockIdx.x * 256 + threadIdx.x;
    float4 v = in[i];
    hi[i] = pack4h(__float2half(v.x), __float2half(v.y),
                   __float2half(v.z), __float2half(v.w));
}

// ================= GEMM1: bf16x3, D[m,n] = sum_k A[m,k]*B[n,k] =================
// 128x128 CTA tile, K-chunk 64, 2-stage cp.async, 8 warps (64x32 warp tile),
// 1 CTA/SM. (Best-measured config: 894us.)
#define TILE_B    16384             // 128 rows * 128B (64 bf16)
#define CHUNK1_B  (4 * TILE_B)      // Ah, Al, Bh, Bl
#define SMEM1_DYN (1024 + 2 * CHUNK1_B)

__global__ __launch_bounds__(256, 1)
void gemm_bf16x3(const __nv_bfloat16* __restrict__ Ah, const __nv_bfloat16* __restrict__ Al,
                 const __nv_bfloat16* __restrict__ Bh, const __nv_bfloat16* __restrict__ Bl,
                 float* __restrict__ C)
{
    extern __shared__ char dsm[];
    const int tid  = threadIdx.x;
    const int warp = tid >> 5;
    const int lane = tid & 31;
    const int b  = blockIdx.z;
    const int m0 = blockIdx.y * 128;
    const int n0 = blockIdx.x * 128;

    const u32 base = (smem_u32(dsm) + 1023u) & ~1023u;
    const int wm = (warp >> 2) * 64;
    const int wn = (warp & 3) * 32;

    // loader: 64 threads per tile (Ah/Al/Bh/Bl); 8 segs x 8 row-bases; 16 rows each
    const size_t bs = (size_t)SEQ * SEQ;
    const int tsel = tid >> 6;
    const int tt   = tid & 63;
    const int seg  = tt & 7;
    const int rb   = tt >> 3;
    const __nv_bfloat16* gbase;
    {
        size_t aoff = (size_t)b * bs + (size_t)m0 * SEQ;
        size_t boff = (size_t)b * bs + (size_t)n0 * SEQ;
        gbase = (tsel == 0) ? Ah + aoff : (tsel == 1) ? Al + aoff
              : (tsel == 2) ? Bh + boff : Bl + boff;
        gbase += (size_t)rb * SEQ + seg * 8;
    }
    u32 soff[16];
#pragma unroll
    for (int j = 0; j < 16; j++)
        soff[j] = SWZ((u32)((rb + 8 * j) * 128 + seg * 16));
    const u32 myTile = base + (u32)tsel * TILE_B;

    const int aRow = ((lane >> 3) & 1) * 8 + (lane & 7);
    const int aCol = (lane >> 4) << 4;
    const int bRow = ((lane >> 4) << 3) + (lane & 7);
    const int bCol = ((lane >> 3) & 1) << 4;

    float acc[4][4][4];
#pragma unroll
    for (int mt = 0; mt < 4; mt++)
#pragma unroll
        for (int nt = 0; nt < 4; nt++)
#pragma unroll
            for (int r = 0; r < 4; r++) acc[mt][nt][r] = 0.0f;

    // double-buffered fragments over k16 steps
    u32 fah[2][4][4], fal[2][4][4], fbh[2][2][4], fbl[2][2][4];

#define FRAG_LOAD1(pb, ks)                                                    \
    do {                                                                      \
        const int kb_ = (ks) * 32;                                            \
        _Pragma("unroll")                                                     \
        for (int mt_ = 0; mt_ < 4; mt_++) {                                   \
            u32 ro_ = SWZ((u32)((wm + mt_ * 16 + aRow) * 128 + kb_ + aCol));  \
            LDM4(fah[pb][mt_], tAh + ro_);                                    \
            LDM4(fal[pb][mt_], tAl + ro_);                                    \
        }                                                                     \
        _Pragma("unroll")                                                     \
        for (int ng_ = 0; ng_ < 2; ng_++) {                                   \
            u32 ro_ = SWZ((u32)((wn + ng_ * 16 + bRow) * 128 + kb_ + bCol));  \
            LDM4(fbh[pb][ng_], tBh + ro_);                                    \
            LDM4(fbl[pb][ng_], tBl + ro_);                                    \
        }                                                                     \
    } while (0)

#define MMA_PHASE1(pb)                                                        \
    do {                                                                      \
        _Pragma("unroll")                                                     \
        for (int mt_ = 0; mt_ < 4; mt_++)                                     \
            _Pragma("unroll")                                                 \
            for (int nt_ = 0; nt_ < 4; nt_++)                                 \
                MMA_BF16(acc[mt_][nt_], fah[pb][mt_],                         \
                         &fbh[pb][nt_ >> 1][(nt_ & 1) * 2]);                  \
        _Pragma("unroll")                                                     \
        for (int mt_ = 0; mt_ < 4; mt_++)                                     \
            _Pragma("unroll")                                                 \
            for (int nt_ = 0; nt_ < 4; nt_++)                                 \
                MMA_BF16(acc[mt_][nt_], fah[pb][mt_],                         \
                         &fbl[pb][nt_ >> 1][(nt_ & 1) * 2]);                  \
        _Pragma("unroll")                                                     \
        for (int mt_ = 0; mt_ < 4; mt_++)                                     \
            _Pragma("unroll")                                                 \
            for (int nt_ = 0; nt_ < 4; nt_++)                                 \
                MMA_BF16(acc[mt_][nt_], fal[pb][mt_],                         \
                         &fbh[pb][nt_ >> 1][(nt_ & 1) * 2]);                  \
    } while (0)

    const int NCHUNK = SEQ / 64;   // 32

    // prologue: chunk 0 -> buffer 0
#pragma unroll
    for (int j = 0; j < 16; j++)
        cpa16(myTile + soff[j], gbase + (size_t)(8 * j) * SEQ);
    CP_COMMIT();
    CP_WAIT0();
    __syncthreads();

    for (int i = 0; i < NCHUNK; i++) {
        const int buf = i & 1;

        if (i + 1 < NCHUNK) {
            const __nv_bfloat16* g = gbase + (i + 1) * 64;
            const u32 st = myTile + (buf ^ 1) * CHUNK1_B;
#pragma unroll
            for (int j = 0; j < 16; j++)
                cpa16(st + soff[j], g + (size_t)(8 * j) * SEQ);
            CP_COMMIT();
        }

        const u32 sb  = base + buf * CHUNK1_B;
        const u32 tAh = sb;
        const u32 tAl = sb + TILE_B;
        const u32 tBh = sb + 2 * TILE_B;
        const u32 tBl = sb + 3 * TILE_B;

        FRAG_LOAD1(0, 0);
#pragma unroll
        for (int ks = 0; ks < 4; ks++) {
            if (ks < 3) FRAG_LOAD1((ks + 1) & 1, ks + 1);
            MMA_PHASE1(ks & 1);
        }

        CP_WAIT0();
        __syncthreads();
    }

    float* Cb = C + (size_t)b * bs;
    const int rrow = lane >> 2;
    const int rcol = (lane & 3) * 2;
#pragma unroll
    for (int mt = 0; mt < 4; mt++) {
#pragma unroll
        for (int nt = 0; nt < 4; nt++) {
            const int row = m0 + wm + mt * 16 + rrow;
            const int col = n0 + wn + nt * 8 + rcol;
            float2 v0; v0.x = acc[mt][nt][0]; v0.y = acc[mt][nt][1];
            float2 v1; v1.x = acc[mt][nt][2]; v1.y = acc[mt][nt][3];
            *(float2*)&Cb[(size_t)row * SEQ + col]       = v0;
            *(float2*)&Cb[(size_t)(row + 8) * SEQ + col] = v1;
        }
    }
}

// ================= GEMM2: single fp16 product, D[m,n] = sum_k A[m,k]*B[n,k] =================
// A = Vh (fp16), B = Ph (fp16 P^T). 128x128 CTA tile, K-chunk 64, 2-stage, 8 warps.
#define CHUNK2_B  (2 * TILE_B)      // Vh, Ph
#define SMEM2_DYN (1024 + 2 * CHUNK2_B)

__global__ __launch_bounds__(256, 1)
void gemm_f16(const __half* __restrict__ Ah, const __half* __restrict__ Bh,
              float* __restrict__ C)
{
    extern __shared__ char dsm[];
    const int tid  = threadIdx.x;
    const int warp = tid >> 5;
    const int lane = tid & 31;
    const int b  = blockIdx.z;
    const int m0 = blockIdx.y * 128;
    const int n0 = blockIdx.x * 128;

    const u32 base = (smem_u32(dsm) + 1023u) & ~1023u;
    const int wm = (warp >> 2) * 64;
    const int wn = (warp & 3) * 32;

    // loader: 128 threads per tile (Vh, Ph); 8 segs x 16 row-bases; 8 rows each
    const size_t bs = (size_t)SEQ * SEQ;
    const int tsel = tid >> 7;        // 0:Vh 1:Ph
    const int tt   = tid & 127;
    const int seg  = tt & 7;
    const int rb   = tt >> 3;         // 0..15
    const __half* gbase;
    {
        size_t aoff = (size_t)b * bs + (size_t)m0 * SEQ;
        size_t boff = (size_t)b * bs + (size_t)n0 * SEQ;
        gbase = (tsel == 0) ? Ah + aoff : Bh + boff;
        gbase += (size_t)rb * SEQ + seg * 8;
    }
    u32 soff[8];
#pragma unroll
    for (int j = 0; j < 8; j++)
        soff[j] = SWZ((u32)((rb + 16 * j) * 128 + seg * 16));
    const u32 myOff = (u32)tsel * TILE_B;

    const int aRow = ((lane >> 3) & 1) * 8 + (lane & 7);
    const int aCol = (lane >> 4) << 4;
    const int bRow = ((lane >> 4) << 3) + (lane & 7);
    const int bCol = ((lane >> 3) & 1) << 4;

    float acc[4][4][4];
#pragma unroll
    for (int mt = 0; mt < 4; mt++)
#pragma unroll
        for (int nt = 0; nt < 4; nt++)
#pragma unroll
            for (int r = 0; r < 4; r++) acc[mt][nt][r] = 0.0f;

    const int NCHUNK = SEQ / 64;

    // prologue: chunk 0 -> buffer 0
#pragma unroll
    for (int j = 0; j < 8; j++)
        cpa16(base + myOff + soff[j], gbase + (size_t)(16 * j) * SEQ);
    CP_COMMIT();
    CP_WAIT0();
    __syncthreads();

    for (int i = 0; i < NCHUNK; i++) {
        const int buf = i & 1;

        if (i + 1 < NCHUNK) {
            const __half* g = gbase + (i + 1) * 64;
            const u32 st = base + (buf ^ 1) * CHUNK2_B + myOff;
#pragma unroll
            for (int j = 0; j < 8; j++)
                cpa16(st + soff[j], g + (size_t)(16 * j) * SEQ);
            CP_COMMIT();
        }

        const u32 sb  = base + buf * CHUNK2_B;
        const u32 tVh = sb;
        const u32 tPh = sb + TILE_B;

#pragma unroll
        for (int ks = 0; ks < 4; ks++) {
            const int kb = ks * 32;
            u32 ah[4][4];
#pragma unroll
            for (int mt = 0; mt < 4; mt++) {
                u32 ro = SWZ((u32)((wm + mt * 16 + aRow) * 128 + kb + aCol));
                LDM4(ah[mt], tVh + ro);
            }
            u32 bh[2][4];
#pragma unroll
            for (int ng = 0; ng < 2; ng++) {
                u32 ro = SWZ((u32)((wn + ng * 16 + bRow) * 128 + kb + bCol));
                LDM4(bh[ng], tPh + ro);
            }
#pragma unroll
            for (int mt = 0; mt < 4; mt++) {
#pragma unroll
                for (int nt = 0; nt < 4; nt++) {
                    MMA_F16(acc[mt][nt], ah[mt], &bh[nt >> 1][(nt & 1) * 2]);
                }
            }
        }

        CP_WAIT0();
        __syncthreads();
    }

    float* Cb = C + (size_t)b * bs;
    const int rrow = lane >> 2;
    const int rcol = (lane & 3) * 2;
#pragma unroll
    for (int mt = 0; mt < 4; mt++) {
#pragma unroll
        for (int nt = 0; nt < 4; nt++) {
            const int row = m0 + wm + mt * 16 + rrow;
            const int col = n0 + wn + nt * 8 + rcol;
            float2 v0; v0.x = acc[mt][nt][0]; v0.y = acc[mt][nt][1];
            float2 v1; v1.x = acc[mt][nt][2]; v1.y = acc[mt][nt][3];
            *(float2*)&Cb[(size_t)row * SEQ + col]       = v0;
            *(float2*)&Cb[(size_t)(row + 8) * SEQ + col] = v1;
        }
    }
}

// ---------------- row softmax (validated) ----------------
__global__ __launch_bounds__(256)
void softmax_rows(float* __restrict__ P)
{
    __shared__ float redm[8];
    __shared__ float reds[8];

    float* p = P + (size_t)blockIdx.x * SEQ;
    const int tid = threadIdx.x;

    float4 v0 = *(const float4*)&p[tid * 8];
    float4 v1 = *(const float4*)&p[tid * 8 + 4];

    float m = fmaxf(fmaxf(fmaxf(v0.x, v0.y), fmaxf(v0.z, v0.w)),
                    fmaxf(fmaxf(v1.x, v1.y), fmaxf(v1.z, v1.w)));
#pragma unroll
    for (int o = 16; o > 0; o >>= 1)
        m = fmaxf(m, __shfl_xor_sync(0xffffffffu, m, o));
    if ((tid & 31) == 0) redm[tid >> 5] = m;
    __syncthreads();
    float bm = redm[0];
#pragma unroll
    for (int i = 1; i < 8; i++) bm = fmaxf(bm, redm[i]);

    float e[8];
    e[0] = __expf(v0.x - bm); e[1] = __expf(v0.y - bm);
    e[2] = __expf(v0.z - bm); e[3] = __expf(v0.w - bm);
    e[4] = __expf(v1.x - bm); e[5] = __expf(v1.y - bm);
    e[6] = __expf(v1.z - bm); e[7] = __expf(v1.w - bm);
    float s = ((e[0] + e[1]) + (e[2] + e[3])) + ((e[4] + e[5]) + (e[6] + e[7]));
#pragma unroll
    for (int o = 16; o > 0; o >>= 1)
        s += __shfl_xor_sync(0xffffffffu, s, o);
    if ((tid & 31) == 0) reds[tid >> 5] = s;
    __syncthreads();
    float total = reds[0];
#pragma unroll
    for (int i = 1; i < 8; i++) total += reds[i];

    const float r = 1.0f / total;
    v0.x = e[0] * r; v0.y = e[1] * r; v0.z = e[2] * r; v0.w = e[3] * r;
    v1.x = e[4] * r; v1.y = e[5] * r; v1.z = e[6] * r; v1.w = e[7] * r;
    *(float4*)&p[tid * 8]     = v0;
    *(float4*)&p[tid * 8 + 4] = v1;
}

// ---------------- transpose + fp16 convert: P[d,k] -> Pt[k,d] ----------------
__global__ __launch_bounds__(256)
void transpose_f16(const float* __restrict__ P, ull* __restrict__ hiT)
{
    __shared__ float s[64][65];
    const int b  = blockIdx.z;
    const int d0 = blockIdx.y * 64;
    const int k0 = blockIdx.x * 64;
    const float* Pb = P + (size_t)b * SEQ * SEQ;
    const int t  = threadIdx.x;
    const int c4 = (t & 15) * 4;
    const int r  = t >> 4;

#pragma unroll
    for (int j = 0; j < 4; j++) {
        int row = r + 16 * j;
        float4 v = *(const float4*)&Pb[(size_t)(d0 + row) * SEQ + k0 + c4];
        s[row][c4 + 0] = v.x; s[row][c4 + 1] = v.y;
        s[row][c4 + 2] = v.z; s[row][c4 + 3] = v.w;
    }
    __syncthreads();
#pragma unroll
    for (int j = 0; j < 4; j++) {
        int trow = r + 16 * j;
        __half h0 = __float2half(s[c4 + 0][trow]);
        __half h1 = __float2half(s[c4 + 1][trow]);
        __half h2 = __float2half(s[c4 + 2][trow]);
        __half h3 = __float2half(s[c4 + 3][trow]);
        size_t oi = ((size_t)b * SEQ * SEQ + (size_t)(k0 + trow) * SEQ + d0 + c4) >> 2;
        hiT[oi] = pack4h(h0, h1, h2, h3);
    }
}

// ---------------- launcher ----------------
extern "C" void kernel_launch(void* const* d_in, const int* in_sizes, int n_in,
                              void* d_out, int out_size)
{
    const float* q = (const float*)d_in[0];
    const float* k = (const float*)d_in[1];
    const float* v = (const float*)d_in[2];
    // d_in[3] = attn_mask: all zeros, unused by the reference math.
    float* out = (float*)d_out;

    float *S = nullptr;
    ull *Qh, *Ql, *Kh, *Kl, *Vh, *Ph;
    cudaGetSymbolAddress((void**)&S,  g_S);
    cudaGetSymbolAddress((void**)&Qh, g_Qh); cudaGetSymbolAddress((void**)&Ql, g_Ql);
    cudaGetSymbolAddress((void**)&Kh, g_Kh); cudaGetSymbolAddress((void**)&Kl, g_Kl);
    cudaGetSymbolAddress((void**)&Vh, g_Vh);
    cudaGetSymbolAddress((void**)&Ph, g_Ph);

    cudaFuncSetAttribute(gemm_bf16x3, cudaFuncAttributeMaxDynamicSharedMemorySize, SMEM1_DYN);
    cudaFuncSetAttribute(gemm_f16,    cudaFuncAttributeMaxDynamicSharedMemorySize, SMEM2_DYN);

    const int splitBlocks = (int)(N4 / 256);          // 32768
    split_bf16 <<<splitBlocks, 256>>>((const float4*)q, Qh, Ql);
    split_bf16 <<<splitBlocks, 256>>>((const float4*)k, Kh, Kl);
    convert_f16<<<splitBlocks, 256>>>((const float4*)v, Vh);

    const dim3 grid(SEQ / 128, SEQ / 128, NB);        // (16, 16, 8) = 2048 CTAs
    // 1) S[q,k] = sum_d Q[q,d] K[k,d]   (bf16x3)
    gemm_bf16x3<<<grid, 256, SMEM1_DYN>>>((const __nv_bfloat16*)Qh, (const __nv_bfloat16*)Ql,
                                          (const __nv_bfloat16*)Kh, (const __nv_bfloat16*)Kl, S);
    // 2) row softmax in place
    softmax_rows<<<NB * SEQ, 256>>>(S);
    // 3) Pt[k2,d] = fp16(P[d,k2])
    transpose_f16<<<dim3(SEQ / 64, SEQ / 64, NB), 256>>>(S, Ph);
    // 4) out[s,k2] = sum_d V[s,d] Pt[k2,d]   (single fp16 product)
    gemm_f16<<<grid, 256, SMEM2_DYN>>>((const __half*)Vh, (const __half*)Ph, out);
}